// round 15
// baseline (speedup 1.0000x reference)
#include <cuda_runtime.h>
#include <cuda_fp16.h>
#include <cstdint>

#define NENT 50000
#define NPAD 50048
#define NREL 500
#define DIM  256
#define BATCH 512
#define EPSF 1e-5f
#define ECS (NENT * DIM)
#define RCS (NREL * DIM)
#define SCTAS 512

// ---------------- scratch (device globals; no allocation APIs) ----------------
__device__ float  g_epart[SCTAS * 2048];          // per-CTA partial sums (deterministic)
__device__ float  g_escale[1024];                 // folded BN scale per (c,d)
__device__ float  g_eshift[1024];                 // folded BN shift per (c,d)
__device__ float  g_hqn[4 * BATCH * DIM];         // qnorm'd gathered h (fp32)
__device__ float  g_hmean[1024];
__device__ float  g_hinvstd[1024];
__device__ float  g_hbias[4 * BATCH];             // per-(c,row) epilogue bias from shift
__device__ __half g_tA[4 * BATCH * DIM];          // fp16 A operand (t * scale)
__device__ __half g_EB[(size_t)4 * NPAD * DIM];   // fp16 B operand (qnorm'd E), padded

__device__ __forceinline__ uint32_t s2u(const void* p) {
    return (uint32_t)__cvta_generic_to_shared(p);
}

// --- 1: qnorm E -> fp16 table + partial stats; CTA b also handles h row b ---
__global__ void k_eqn(const float* __restrict__ E, const int* __restrict__ h_idx) {
    const int d = threadIdx.x;
    const int b = blockIdx.x;
    float s0 = 0.f, s1 = 0.f, s2 = 0.f, s3 = 0.f;
    float q0 = 0.f, q1 = 0.f, q2 = 0.f, q3 = 0.f;
    for (int n = b; n < NPAD; n += SCTAS) {
        const size_t o = (size_t)n * DIM + d;
        if (n < NENT) {
            float e0 = E[0 * (size_t)ECS + o];
            float e1 = E[1 * (size_t)ECS + o];
            float e2 = E[2 * (size_t)ECS + o];
            float e3 = E[3 * (size_t)ECS + o];
            float il = rsqrtf(e0 * e0 + e1 * e1 + e2 * e2 + e3 * e3);
            float c0 = e0 * il, c1 = e1 * il, c2 = e2 * il, c3 = e3 * il;
            g_EB[0 * (size_t)NPAD * DIM + o] = __float2half(c0);
            g_EB[1 * (size_t)NPAD * DIM + o] = __float2half(c1);
            g_EB[2 * (size_t)NPAD * DIM + o] = __float2half(c2);
            g_EB[3 * (size_t)NPAD * DIM + o] = __float2half(c3);
            s0 += c0; q0 += c0 * c0;
            s1 += c1; q1 += c1 * c1;
            s2 += c2; q2 += c2 * c2;
            s3 += c3; q3 += c3 * c3;
        } else {
            g_EB[0 * (size_t)NPAD * DIM + o] = __float2half(0.f);
            g_EB[1 * (size_t)NPAD * DIM + o] = __float2half(0.f);
            g_EB[2 * (size_t)NPAD * DIM + o] = __float2half(0.f);
            g_EB[3 * (size_t)NPAD * DIM + o] = __float2half(0.f);
        }
    }
    float* p = g_epart + b * 2048;
    p[0 * 512 + d * 2] = s0;  p[0 * 512 + d * 2 + 1] = q0;
    p[1 * 512 + d * 2] = s1;  p[1 * 512 + d * 2 + 1] = q1;
    p[2 * 512 + d * 2] = s2;  p[2 * 512 + d * 2 + 1] = q2;
    p[3 * 512 + d * 2] = s3;  p[3 * 512 + d * 2 + 1] = q3;

    // fused former k_hqn: gather + qnorm batch row b (SCTAS == BATCH)
    {
        const int n = h_idx[b];
        float e0 = E[0 * (size_t)ECS + (size_t)n * DIM + d];
        float e1 = E[1 * (size_t)ECS + (size_t)n * DIM + d];
        float e2 = E[2 * (size_t)ECS + (size_t)n * DIM + d];
        float e3 = E[3 * (size_t)ECS + (size_t)n * DIM + d];
        float il = rsqrtf(e0 * e0 + e1 * e1 + e2 * e2 + e3 * e3);
        g_hqn[0 * (BATCH * DIM) + b * DIM + d] = e0 * il;
        g_hqn[1 * (BATCH * DIM) + b * DIM + d] = e1 * il;
        g_hqn[2 * (BATCH * DIM) + b * DIM + d] = e2 * il;
        g_hqn[3 * (BATCH * DIM) + b * DIM + d] = e3 * il;
    }
}

// --- 2: merged stats finalize: blocks [0,1024) = E-stats fold; [1024,1056) = h BN ---
__global__ void k_stats(const float* __restrict__ gamma, const float* __restrict__ beta) {
    __shared__ float rs[256], rq[256];
    const int bx = blockIdx.x;
    const int i  = threadIdx.x;
    if (bx < 1024) {
        const int t = bx;
        float s = g_epart[i * 2048 + t * 2]     + g_epart[(i + 256) * 2048 + t * 2];
        float q = g_epart[i * 2048 + t * 2 + 1] + g_epart[(i + 256) * 2048 + t * 2 + 1];
        rs[i] = s; rq[i] = q;
        __syncthreads();
        for (int w = 128; w > 0; w >>= 1) {
            if (i < w) { rs[i] += rs[i + w]; rq[i] += rq[i + w]; }
            __syncthreads();
        }
        if (i == 0) {
            float mean = rs[0] * (1.f / NENT);
            float var  = rq[0] * (1.f / NENT) - mean * mean;
            float sc   = gamma[t] * rsqrtf(var + EPSF);
            g_escale[t] = sc;
            g_eshift[t] = beta[t] - mean * sc;
        }
    } else {
        const int blk = bx - 1024;
        const int c   = blk >> 3;
        const int d   = (blk & 7) * 32 + (i >> 3);
        const int j   = i & 7;
        float s = 0.f, q = 0.f;
        for (int b = j; b < BATCH; b += 8) {
            float v = g_hqn[c * (BATCH * DIM) + b * DIM + d];
            s += v; q += v * v;
        }
        rs[i] = s; rq[i] = q;
        __syncthreads();
        for (int w = 4; w > 0; w >>= 1) {
            if (j < w) { rs[i] += rs[i + w]; rq[i] += rq[i + w]; }
            __syncthreads();
        }
        if (j == 0) {
            float mean = rs[i] * (1.f / BATCH);
            float var  = rq[i] * (1.f / BATCH) - mean * mean;
            g_hmean[c * DIM + d]   = mean;
            g_hinvstd[c * DIM + d] = rsqrtf(var + EPSF);
        }
    }
}

// --- 3: BN(h), qnorm(r), quaternion mult -> fp16 A + hbias (shuffle reduce) ---
__global__ void k_t(const float* __restrict__ R, const float* __restrict__ psi,
                    const float* __restrict__ gamma, const float* __restrict__ beta,
                    const int* __restrict__ r_idx) {
    __shared__ float red[8][4];
    const int d = threadIdx.x;
    const int b = blockIdx.x;
    const int lid = d & 31, wrp = d >> 5;
    const int rid = r_idx[b];
    float h[4], r[4];
#pragma unroll
    for (int c = 0; c < 4; c++) {
        float v = g_hqn[c * (BATCH * DIM) + b * DIM + d];
        h[c] = (v - g_hmean[c * DIM + d]) * g_hinvstd[c * DIM + d] * gamma[c * DIM + d]
               + beta[c * DIM + d];
        r[c] = R[c * (size_t)RCS + (size_t)rid * DIM + d];
    }
    float il = rsqrtf(r[0] * r[0] + r[1] * r[1] + r[2] * r[2] + r[3] * r[3]);
    r[0] *= il; r[1] *= il; r[2] *= il; r[3] *= il;
    float p  = psi[(size_t)rid * DIM + d];
    float zc = cosf(p), zs = sinf(p);
    float m1r = h[0] * r[0] - h[1] * r[1];
    float m1i = h[0] * r[1] + h[1] * r[0];
    float Xr = h[2] * r[2] + h[3] * r[3];
    float Xi = h[3] * r[2] - h[2] * r[3];
    float m2r = zc * Xr - zs * Xi, m2i = zc * Xi + zs * Xr;
    float m3r = h[0] * r[2] - h[1] * r[3];
    float m3i = h[0] * r[3] + h[1] * r[2];
    float Yr = h[2] * r[0] + h[3] * r[1];
    float Yi = h[3] * r[0] - h[2] * r[1];
    float m4r = zc * Yr - zs * Yi, m4i = zc * Yi + zs * Yr;
    float t[4] = { m1r - m2r, m1i - m2i, m3r + m4r, m3i + m4i };

    float v[4];
#pragma unroll
    for (int c = 0; c < 4; c++) {
        float sc = g_escale[c * DIM + d], sh = g_eshift[c * DIM + d];
        g_tA[c * (BATCH * DIM) + b * DIM + d] = __float2half(t[c] * sc);
        v[c] = t[c] * sh;
#pragma unroll
        for (int o = 16; o > 0; o >>= 1)
            v[c] += __shfl_xor_sync(0xFFFFFFFFu, v[c], o);
    }
    if (lid == 0) {
        red[wrp][0] = v[0]; red[wrp][1] = v[1];
        red[wrp][2] = v[2]; red[wrp][3] = v[3];
    }
    __syncthreads();
    if (d < 4) {
        float s = 0.f;
#pragma unroll
        for (int w = 0; w < 8; w++) s += red[w][d];
        g_hbias[d * BATCH + b] = s;
    }
}

// --- 4: HMMA GEMM: 128x64 tile, 32x32 warp tile, 4 CTA/SM, unrolled 2-stage ---
#define KTILE 64
#define NTILE 64
#define STRIDE 72                         /* fp16 per smem row (64 + 8 pad)       */
#define AROWS 128
#define BROWS 64
#define AELEMS (AROWS * STRIDE)
#define STAGE_BYTES ((AROWS + BROWS) * STRIDE * 2)   /* 27648 */
#define GEMM_SMEM (2 * STAGE_BYTES)                  /* 55296; 4 CTAs = 221184   */

__device__ __forceinline__ void ldmx4(uint32_t* r, uint32_t addr) {
    asm volatile(
        "ldmatrix.sync.aligned.m8n8.x4.shared.b16 {%0,%1,%2,%3}, [%4];"
        : "=r"(r[0]), "=r"(r[1]), "=r"(r[2]), "=r"(r[3]) : "r"(addr));
}

__device__ __forceinline__ void mma16816(float* c, const uint32_t* a,
                                         uint32_t b0, uint32_t b1) {
    asm volatile(
        "mma.sync.aligned.m16n8k16.row.col.f32.f16.f16.f32 "
        "{%0,%1,%2,%3}, {%4,%5,%6,%7}, {%8,%9}, {%0,%1,%2,%3};"
        : "+f"(c[0]), "+f"(c[1]), "+f"(c[2]), "+f"(c[3])
        : "r"(a[0]), "r"(a[1]), "r"(a[2]), "r"(a[3]), "r"(b0), "r"(b1));
}

// sigmoid(2*xh) = 0.5 + 0.5*tanh(xh): single MUFU.TANH.
__device__ __forceinline__ float fsig2(float xh) {
    float t;
    asm("tanh.approx.f32 %0, %1;" : "=f"(t) : "f"(xh));
    return fmaf(t, 0.5f, 0.5f);
}

__global__ void __launch_bounds__(256, 4) k_gemm(const float* __restrict__ biases,
                                                 float* __restrict__ out) {
    extern __shared__ __align__(128) __half sh[];
    const int tid = threadIdx.x;
    const int lid = tid & 31, wid = tid >> 5;
    const int m0 = blockIdx.x * 128, n0 = blockIdx.y * NTILE, comp = blockIdx.z;
    const int wm = (wid & 3) * 32;      // 4 warps along m (32 rows each)
    const int wn = (wid >> 2) * 32;     // 2 warps along n (32 cols each)

    const __half* Ag = g_tA + ((size_t)comp * BATCH + m0) * DIM;
    const __half* Bg = g_EB + ((size_t)comp * NPAD + n0) * DIM;
    const uint32_t sbase = s2u(sh);

    // Stage fill: A 128 rows + B 64 rows, 8 x 16B chunks per row.
    auto load_stage = [&](int kc, int s) {
        const uint32_t sa = sbase + s * STAGE_BYTES;
        const uint32_t sb = sa + AELEMS * 2;
#pragma unroll
        for (int j = 0; j < 4; j++) {       // A: ids 0..1023
            int id = tid + j * 256;
            int row = id >> 3, c = id & 7;
            uint32_t da = sa + (row * STRIDE + c * 8) * 2;
            const __half* ga = Ag + row * DIM + kc * KTILE + c * 8;
            asm volatile("cp.async.cg.shared.global [%0], [%1], 16;"
                         :: "r"(da), "l"(ga));
        }
#pragma unroll
        for (int j = 0; j < 2; j++) {       // B: ids 0..511
            int id = tid + j * 256;
            int row = id >> 3, c = id & 7;
            uint32_t db = sb + (row * STRIDE + c * 8) * 2;
            const __half* gb = Bg + row * DIM + kc * KTILE + c * 8;
            asm volatile("cp.async.cg.shared.global [%0], [%1], 16;"
                         :: "r"(db), "l"(gb));
        }
        asm volatile("cp.async.commit_group;" ::: "memory");
    };

    float acc[2][4][4];
#pragma unroll
    for (int mi = 0; mi < 2; mi++)
#pragma unroll
        for (int ni = 0; ni < 4; ni++)
#pragma unroll
            for (int f = 0; f < 4; f++) acc[mi][ni][f] = 0.f;

    load_stage(0, 0);
    load_stage(1, 1);

    const int lrow = lid & 15;
    const int lk   = (lid >> 4) * 8;

    // Per-warp smem base addresses (stage 0); all ldmatrix addresses below are
    // base + compile-time immediates -> SASS LDSM [R+imm], no per-ld IMADs.
    const uint32_t aw = sbase + ((wm + lrow) * STRIDE + lk) * 2;
    const uint32_t bw = sbase + AELEMS * 2 + ((wn + lrow) * STRIDE + lk) * 2;

    auto compute = [&](uint32_t soff) {
        const uint32_t sa = aw + soff;
        const uint32_t sb = bw + soff;
#pragma unroll
        for (int ks = 0; ks < 4; ks++) {
            uint32_t a[2][4], bf[2][4];
            ldmx4(a[0],  sa + ks * 32);
            ldmx4(a[1],  sa + 16 * STRIDE * 2 + ks * 32);
            ldmx4(bf[0], sb + ks * 32);
            ldmx4(bf[1], sb + 16 * STRIDE * 2 + ks * 32);
#pragma unroll
            for (int mi = 0; mi < 2; mi++)
#pragma unroll
                for (int ni = 0; ni < 4; ni++)
                    mma16816(acc[mi][ni], a[mi],
                             bf[ni >> 1][ni & 1], bf[ni >> 1][(ni & 1) + 2]);
        }
    };

    // Fully unrolled 2-stage schedule; ledger identical to the rolled R14 loop:
    //   wait1 -> compute(0) -> load(2,0); wait1 -> compute(1) -> load(3,1);
    //   wait1 -> compute(0);              wait0 -> compute(1).
    asm volatile("cp.async.wait_group 1;" ::: "memory");
    __syncthreads();
    compute(0);
    __syncthreads();
    load_stage(2, 0);
    asm volatile("cp.async.wait_group 1;" ::: "memory");
    __syncthreads();
    compute(STAGE_BYTES);
    __syncthreads();
    load_stage(3, 1);
    asm volatile("cp.async.wait_group 1;" ::: "memory");
    __syncthreads();
    compute(0);
    asm volatile("cp.async.wait_group 0;" ::: "memory");
    __syncthreads();
    compute(STAGE_BYTES);

    // ---- epilogue (mi-outer form): tanh sigmoid, float2 stores ----
    const float* bi = biases + (size_t)comp * NENT;
    float* op = out + (size_t)comp * BATCH * NENT;
#pragma unroll
    for (int mi = 0; mi < 2; mi++) {
        const int r0 = m0 + wm + mi * 16 + (lid >> 2);
        const float hb0 = 0.5f * g_hbias[comp * BATCH + r0];
        const float hb1 = 0.5f * g_hbias[comp * BATCH + r0 + 8];
#pragma unroll
        for (int ni = 0; ni < 4; ni++) {
            const int n = n0 + wn + ni * 8 + (lid & 3) * 2;
            if (n < NENT) {   // NENT even -> pair-level mask exact
                const float b0v = 0.5f * bi[n], b1v = 0.5f * bi[n + 1];
                float2 v0, v1;
                v0.x = fsig2(fmaf(acc[mi][ni][0], 0.5f, hb0 + b0v));
                v0.y = fsig2(fmaf(acc[mi][ni][1], 0.5f, hb0 + b1v));
                v1.x = fsig2(fmaf(acc[mi][ni][2], 0.5f, hb1 + b0v));
                v1.y = fsig2(fmaf(acc[mi][ni][3], 0.5f, hb1 + b1v));
                *reinterpret_cast<float2*>(op + (size_t)r0 * NENT + n) = v0;
                *reinterpret_cast<float2*>(op + (size_t)(r0 + 8) * NENT + n) = v1;
            }
        }
    }
}

// ---------------- launch ----------------
extern "C" void kernel_launch(void* const* d_in, const int* in_sizes, int n_in,
                              void* d_out, int out_size) {
    (void)in_sizes; (void)n_in; (void)out_size;
    const float* E      = (const float*)d_in[0];
    const float* R      = (const float*)d_in[1];
    const float* psi    = (const float*)d_in[2];
    const float* gamma  = (const float*)d_in[3];
    const float* beta   = (const float*)d_in[4];
    const float* biases = (const float*)d_in[5];
    const int*   h_idx  = (const int*)d_in[6];
    const int*   r_idx  = (const int*)d_in[7];
    float* out = (float*)d_out;

    cudaFuncSetAttribute(k_gemm, cudaFuncAttributeMaxDynamicSharedMemorySize,
                         GEMM_SMEM);

    k_eqn<<<SCTAS, DIM>>>(E, h_idx);
    k_stats<<<1056, 256>>>(gamma, beta);
    k_t<<<BATCH, DIM>>>(R, psi, gamma, beta, r_idx);
    k_gemm<<<dim3(4, NPAD / NTILE, 4), 256, GEMM_SMEM>>>(biases, out);
}

// round 16
// speedup vs baseline: 1.1411x; 1.1411x over previous
#include <cuda_runtime.h>
#include <cuda_fp16.h>
#include <cstdint>

#define NENT 50000
#define NPAD 50048
#define NREL 500
#define DIM  256
#define BATCH 512
#define EPSF 1e-5f
#define ECS (NENT * DIM)
#define RCS (NREL * DIM)
#define SCTAS 512

// ---------------- scratch (device globals; no allocation APIs) ----------------
__device__ float  g_epart[SCTAS * 2048];          // per-CTA partial sums (deterministic)
__device__ float  g_escale[1024];                 // folded BN scale per (c,d)
__device__ float  g_eshift[1024];                 // folded BN shift per (c,d)
__device__ float  g_hqn[4 * BATCH * DIM];         // qnorm'd gathered h (fp32)
__device__ float  g_hmean[1024];
__device__ float  g_hinvstd[1024];
__device__ float  g_hbias[4 * BATCH];             // per-(c,row) epilogue bias from shift
__device__ __half g_tA[4 * BATCH * DIM];          // fp16 A operand (t * scale)
__device__ __half g_EB[(size_t)4 * NPAD * DIM];   // fp16 B operand (qnorm'd E), padded

__device__ __forceinline__ uint32_t s2u(const void* p) {
    return (uint32_t)__cvta_generic_to_shared(p);
}

// --- 1: qnorm E -> fp16 table + partial stats; CTA b also handles h row b ---
__global__ void k_eqn(const float* __restrict__ E, const int* __restrict__ h_idx) {
    const int d = threadIdx.x;
    const int b = blockIdx.x;
    float s0 = 0.f, s1 = 0.f, s2 = 0.f, s3 = 0.f;
    float q0 = 0.f, q1 = 0.f, q2 = 0.f, q3 = 0.f;
    for (int n = b; n < NPAD; n += SCTAS) {
        const size_t o = (size_t)n * DIM + d;
        if (n < NENT) {
            float e0 = E[0 * (size_t)ECS + o];
            float e1 = E[1 * (size_t)ECS + o];
            float e2 = E[2 * (size_t)ECS + o];
            float e3 = E[3 * (size_t)ECS + o];
            float il = rsqrtf(e0 * e0 + e1 * e1 + e2 * e2 + e3 * e3);
            float c0 = e0 * il, c1 = e1 * il, c2 = e2 * il, c3 = e3 * il;
            g_EB[0 * (size_t)NPAD * DIM + o] = __float2half(c0);
            g_EB[1 * (size_t)NPAD * DIM + o] = __float2half(c1);
            g_EB[2 * (size_t)NPAD * DIM + o] = __float2half(c2);
            g_EB[3 * (size_t)NPAD * DIM + o] = __float2half(c3);
            s0 += c0; q0 += c0 * c0;
            s1 += c1; q1 += c1 * c1;
            s2 += c2; q2 += c2 * c2;
            s3 += c3; q3 += c3 * c3;
        } else {
            g_EB[0 * (size_t)NPAD * DIM + o] = __float2half(0.f);
            g_EB[1 * (size_t)NPAD * DIM + o] = __float2half(0.f);
            g_EB[2 * (size_t)NPAD * DIM + o] = __float2half(0.f);
            g_EB[3 * (size_t)NPAD * DIM + o] = __float2half(0.f);
        }
    }
    float* p = g_epart + b * 2048;
    p[0 * 512 + d * 2] = s0;  p[0 * 512 + d * 2 + 1] = q0;
    p[1 * 512 + d * 2] = s1;  p[1 * 512 + d * 2 + 1] = q1;
    p[2 * 512 + d * 2] = s2;  p[2 * 512 + d * 2 + 1] = q2;
    p[3 * 512 + d * 2] = s3;  p[3 * 512 + d * 2 + 1] = q3;

    // fused former k_hqn: gather + qnorm batch row b (SCTAS == BATCH)
    {
        const int n = h_idx[b];
        float e0 = E[0 * (size_t)ECS + (size_t)n * DIM + d];
        float e1 = E[1 * (size_t)ECS + (size_t)n * DIM + d];
        float e2 = E[2 * (size_t)ECS + (size_t)n * DIM + d];
        float e3 = E[3 * (size_t)ECS + (size_t)n * DIM + d];
        float il = rsqrtf(e0 * e0 + e1 * e1 + e2 * e2 + e3 * e3);
        g_hqn[0 * (BATCH * DIM) + b * DIM + d] = e0 * il;
        g_hqn[1 * (BATCH * DIM) + b * DIM + d] = e1 * il;
        g_hqn[2 * (BATCH * DIM) + b * DIM + d] = e2 * il;
        g_hqn[3 * (BATCH * DIM) + b * DIM + d] = e3 * il;
    }
}

// --- 2: merged stats finalize: blocks [0,1024) = E-stats fold; [1024,1056) = h BN ---
__global__ void k_stats(const float* __restrict__ gamma, const float* __restrict__ beta) {
    __shared__ float rs[256], rq[256];
    const int bx = blockIdx.x;
    const int i  = threadIdx.x;
    if (bx < 1024) {
        const int t = bx;
        float s = g_epart[i * 2048 + t * 2]     + g_epart[(i + 256) * 2048 + t * 2];
        float q = g_epart[i * 2048 + t * 2 + 1] + g_epart[(i + 256) * 2048 + t * 2 + 1];
        rs[i] = s; rq[i] = q;
        __syncthreads();
        for (int w = 128; w > 0; w >>= 1) {
            if (i < w) { rs[i] += rs[i + w]; rq[i] += rq[i + w]; }
            __syncthreads();
        }
        if (i == 0) {
            float mean = rs[0] * (1.f / NENT);
            float var  = rq[0] * (1.f / NENT) - mean * mean;
            float sc   = gamma[t] * rsqrtf(var + EPSF);
            g_escale[t] = sc;
            g_eshift[t] = beta[t] - mean * sc;
        }
    } else {
        const int blk = bx - 1024;
        const int c   = blk >> 3;
        const int d   = (blk & 7) * 32 + (i >> 3);
        const int j   = i & 7;
        float s = 0.f, q = 0.f;
        for (int b = j; b < BATCH; b += 8) {
            float v = g_hqn[c * (BATCH * DIM) + b * DIM + d];
            s += v; q += v * v;
        }
        rs[i] = s; rq[i] = q;
        __syncthreads();
        for (int w = 4; w > 0; w >>= 1) {
            if (j < w) { rs[i] += rs[i + w]; rq[i] += rq[i + w]; }
            __syncthreads();
        }
        if (j == 0) {
            float mean = rs[i] * (1.f / BATCH);
            float var  = rq[i] * (1.f / BATCH) - mean * mean;
            g_hmean[c * DIM + d]   = mean;
            g_hinvstd[c * DIM + d] = rsqrtf(var + EPSF);
        }
    }
}

// --- 3: BN(h), qnorm(r), quaternion mult -> fp16 A + hbias (shuffle reduce) ---
__global__ void k_t(const float* __restrict__ R, const float* __restrict__ psi,
                    const float* __restrict__ gamma, const float* __restrict__ beta,
                    const int* __restrict__ r_idx) {
    __shared__ float red[8][4];
    const int d = threadIdx.x;
    const int b = blockIdx.x;
    const int lid = d & 31, wrp = d >> 5;
    const int rid = r_idx[b];
    float h[4], r[4];
#pragma unroll
    for (int c = 0; c < 4; c++) {
        float v = g_hqn[c * (BATCH * DIM) + b * DIM + d];
        h[c] = (v - g_hmean[c * DIM + d]) * g_hinvstd[c * DIM + d] * gamma[c * DIM + d]
               + beta[c * DIM + d];
        r[c] = R[c * (size_t)RCS + (size_t)rid * DIM + d];
    }
    float il = rsqrtf(r[0] * r[0] + r[1] * r[1] + r[2] * r[2] + r[3] * r[3]);
    r[0] *= il; r[1] *= il; r[2] *= il; r[3] *= il;
    float p  = psi[(size_t)rid * DIM + d];
    float zc = cosf(p), zs = sinf(p);
    float m1r = h[0] * r[0] - h[1] * r[1];
    float m1i = h[0] * r[1] + h[1] * r[0];
    float Xr = h[2] * r[2] + h[3] * r[3];
    float Xi = h[3] * r[2] - h[2] * r[3];
    float m2r = zc * Xr - zs * Xi, m2i = zc * Xi + zs * Xr;
    float m3r = h[0] * r[2] - h[1] * r[3];
    float m3i = h[0] * r[3] + h[1] * r[2];
    float Yr = h[2] * r[0] + h[3] * r[1];
    float Yi = h[3] * r[0] - h[2] * r[1];
    float m4r = zc * Yr - zs * Yi, m4i = zc * Yi + zs * Yr;
    float t[4] = { m1r - m2r, m1i - m2i, m3r + m4r, m3i + m4i };

    float v[4];
#pragma unroll
    for (int c = 0; c < 4; c++) {
        float sc = g_escale[c * DIM + d], sh = g_eshift[c * DIM + d];
        g_tA[c * (BATCH * DIM) + b * DIM + d] = __float2half(t[c] * sc);
        v[c] = t[c] * sh;
#pragma unroll
        for (int o = 16; o > 0; o >>= 1)
            v[c] += __shfl_xor_sync(0xFFFFFFFFu, v[c], o);
    }
    if (lid == 0) {
        red[wrp][0] = v[0]; red[wrp][1] = v[1];
        red[wrp][2] = v[2]; red[wrp][3] = v[3];
    }
    __syncthreads();
    if (d < 4) {
        float s = 0.f;
#pragma unroll
        for (int w = 0; w < 8; w++) s += red[w][d];
        g_hbias[d * BATCH + b] = s;
    }
}

// --- 4: HMMA GEMM: 128x64 tile, 32x32 warp tile, 4 CTA/SM, rolled 2-stage ---
#define KTILE 64
#define NTILE 64
#define STRIDE 72                         /* fp16 per smem row (64 + 8 pad)       */
#define AROWS 128
#define BROWS 64
#define AELEMS (AROWS * STRIDE)
#define STAGE_BYTES ((AROWS + BROWS) * STRIDE * 2)   /* 27648 */
#define GEMM_SMEM (2 * STAGE_BYTES)                  /* 55296; 4 CTAs = 221184   */

__device__ __forceinline__ void ldmx4(uint32_t* r, uint32_t addr) {
    asm volatile(
        "ldmatrix.sync.aligned.m8n8.x4.shared.b16 {%0,%1,%2,%3}, [%4];"
        : "=r"(r[0]), "=r"(r[1]), "=r"(r[2]), "=r"(r[3]) : "r"(addr));
}

__device__ __forceinline__ void mma16816(float* c, const uint32_t* a,
                                         uint32_t b0, uint32_t b1) {
    asm volatile(
        "mma.sync.aligned.m16n8k16.row.col.f32.f16.f16.f32 "
        "{%0,%1,%2,%3}, {%4,%5,%6,%7}, {%8,%9}, {%0,%1,%2,%3};"
        : "+f"(c[0]), "+f"(c[1]), "+f"(c[2]), "+f"(c[3])
        : "r"(a[0]), "r"(a[1]), "r"(a[2]), "r"(a[3]), "r"(b0), "r"(b1));
}

// sigmoid(2*xh) = 0.5 + 0.5*tanh(xh): single MUFU.TANH.
__device__ __forceinline__ float fsig2(float xh) {
    float t;
    asm("tanh.approx.f32 %0, %1;" : "=f"(t) : "f"(xh));
    return fmaf(t, 0.5f, 0.5f);
}

__global__ void __launch_bounds__(256, 4) k_gemm(const float* __restrict__ biases,
                                                 float* __restrict__ out) {
    extern __shared__ __align__(128) __half sh[];
    const int tid = threadIdx.x;
    const int lid = tid & 31, wid = tid >> 5;
    const int m0 = blockIdx.x * 128, n0 = blockIdx.y * NTILE, comp = blockIdx.z;
    const int wm = (wid & 3) * 32;      // 4 warps along m (32 rows each)
    const int wn = (wid >> 2) * 32;     // 2 warps along n (32 cols each)

    const __half* Ag = g_tA + ((size_t)comp * BATCH + m0) * DIM;
    const __half* Bg = g_EB + ((size_t)comp * NPAD + n0) * DIM;
    const uint32_t sbase = s2u(sh);

    // Stage fill: A 128 rows + B 64 rows, 8 x 16B chunks per row.
    auto load_stage = [&](int kc, int s) {
        const uint32_t sa = sbase + s * STAGE_BYTES;
        const uint32_t sb = sa + AELEMS * 2;
#pragma unroll
        for (int j = 0; j < 4; j++) {       // A: ids 0..1023
            int id = tid + j * 256;
            int row = id >> 3, c = id & 7;
            uint32_t da = sa + (row * STRIDE + c * 8) * 2;
            const __half* ga = Ag + row * DIM + kc * KTILE + c * 8;
            asm volatile("cp.async.cg.shared.global [%0], [%1], 16;"
                         :: "r"(da), "l"(ga));
        }
#pragma unroll
        for (int j = 0; j < 2; j++) {       // B: ids 0..511
            int id = tid + j * 256;
            int row = id >> 3, c = id & 7;
            uint32_t db = sb + (row * STRIDE + c * 8) * 2;
            const __half* gb = Bg + row * DIM + kc * KTILE + c * 8;
            asm volatile("cp.async.cg.shared.global [%0], [%1], 16;"
                         :: "r"(db), "l"(gb));
        }
        asm volatile("cp.async.commit_group;" ::: "memory");
    };

    float acc[2][4][4];
#pragma unroll
    for (int mi = 0; mi < 2; mi++)
#pragma unroll
        for (int ni = 0; ni < 4; ni++)
#pragma unroll
            for (int f = 0; f < 4; f++) acc[mi][ni][f] = 0.f;

    load_stage(0, 0);
    load_stage(1, 1);

    const int lrow = lid & 15;
    const int lk   = (lid >> 4) * 8;

    // Per-warp smem base addresses (stage 0). Inside the rolled loop every
    // ldmatrix address is base + soff + compile-time-imm -> LDSM [R+imm]
    // (2 IADDs per iteration vs 16 per-ld address chains). Rolled loop keeps
    // the body ~1KB -> L0 I-cache resident (the R15 full unroll blew L0).
    const uint32_t aw = sbase + ((wm + lrow) * STRIDE + lk) * 2;
    const uint32_t bw = sbase + AELEMS * 2 + ((wn + lrow) * STRIDE + lk) * 2;

    // 2-stage ledger: entering kc, in-flight groups {kc, min(kc+1,3)}.
    // kc<3: wait_group 1 -> group kc done. kc==3: wait_group 0.
    // Post-compute barrier only needed when a load overwrites the stage (kc<2).
#pragma unroll 1
    for (int kc = 0; kc < 4; kc++) {
        if (kc < 3) {
            asm volatile("cp.async.wait_group 1;" ::: "memory");
        } else {
            asm volatile("cp.async.wait_group 0;" ::: "memory");
        }
        __syncthreads();
        const uint32_t soff = (uint32_t)(kc & 1) * STAGE_BYTES;
        const uint32_t sa = aw + soff;
        const uint32_t sb = bw + soff;
#pragma unroll
        for (int ks = 0; ks < 4; ks++) {
            uint32_t a[2][4], bf[2][4];
            ldmx4(a[0],  sa + ks * 32);
            ldmx4(a[1],  sa + 16 * STRIDE * 2 + ks * 32);
            ldmx4(bf[0], sb + ks * 32);
            ldmx4(bf[1], sb + 16 * STRIDE * 2 + ks * 32);
#pragma unroll
            for (int mi = 0; mi < 2; mi++)
#pragma unroll
                for (int ni = 0; ni < 4; ni++)
                    mma16816(acc[mi][ni], a[mi],
                             bf[ni >> 1][ni & 1], bf[ni >> 1][(ni & 1) + 2]);
        }
        if (kc < 2) {
            __syncthreads();
            load_stage(kc + 2, kc & 1);
        }
    }

    // ---- epilogue (mi-outer form): tanh sigmoid, float2 stores ----
    const float* bi = biases + (size_t)comp * NENT;
    float* op = out + (size_t)comp * BATCH * NENT;
#pragma unroll
    for (int mi = 0; mi < 2; mi++) {
        const int r0 = m0 + wm + mi * 16 + (lid >> 2);
        const float hb0 = 0.5f * g_hbias[comp * BATCH + r0];
        const float hb1 = 0.5f * g_hbias[comp * BATCH + r0 + 8];
#pragma unroll
        for (int ni = 0; ni < 4; ni++) {
            const int n = n0 + wn + ni * 8 + (lid & 3) * 2;
            if (n < NENT) {   // NENT even -> pair-level mask exact
                const float b0v = 0.5f * bi[n], b1v = 0.5f * bi[n + 1];
                float2 v0, v1;
                v0.x = fsig2(fmaf(acc[mi][ni][0], 0.5f, hb0 + b0v));
                v0.y = fsig2(fmaf(acc[mi][ni][1], 0.5f, hb0 + b1v));
                v1.x = fsig2(fmaf(acc[mi][ni][2], 0.5f, hb1 + b0v));
                v1.y = fsig2(fmaf(acc[mi][ni][3], 0.5f, hb1 + b1v));
                *reinterpret_cast<float2*>(op + (size_t)r0 * NENT + n) = v0;
                *reinterpret_cast<float2*>(op + (size_t)(r0 + 8) * NENT + n) = v1;
            }
        }
    }
}

// ---------------- launch ----------------
extern "C" void kernel_launch(void* const* d_in, const int* in_sizes, int n_in,
                              void* d_out, int out_size) {
    (void)in_sizes; (void)n_in; (void)out_size;
    const float* E      = (const float*)d_in[0];
    const float* R      = (const float*)d_in[1];
    const float* psi    = (const float*)d_in[2];
    const float* gamma  = (const float*)d_in[3];
    const float* beta   = (const float*)d_in[4];
    const float* biases = (const float*)d_in[5];
    const int*   h_idx  = (const int*)d_in[6];
    const int*   r_idx  = (const int*)d_in[7];
    float* out = (float*)d_out;

    cudaFuncSetAttribute(k_gemm, cudaFuncAttributeMaxDynamicSharedMemorySize,
                         GEMM_SMEM);

    k_eqn<<<SCTAS, DIM>>>(E, h_idx);
    k_stats<<<1056, 256>>>(gamma, beta);
    k_t<<<BATCH, DIM>>>(R, psi, gamma, beta, r_idx);
    k_gemm<<<dim3(4, NPAD / NTILE, 4), 256, GEMM_SMEM>>>(biases, out);
}

// round 17
// speedup vs baseline: 1.1555x; 1.0126x over previous
#include <cuda_runtime.h>
#include <cuda_fp16.h>
#include <cstdint>

#define NENT 50000
#define NPAD 50048
#define NREL 500
#define DIM  256
#define BATCH 512
#define EPSF 1e-5f
#define ECS (NENT * DIM)
#define RCS (NREL * DIM)
#define SCTAS 512

// ---------------- scratch (device globals; no allocation APIs) ----------------
__device__ float  g_epart[SCTAS * 2048];          // per-CTA partial sums (deterministic)
__device__ float  g_escale[1024];                 // folded BN scale per (c,d)
__device__ float  g_eshift[1024];                 // folded BN shift per (c,d)
__device__ float  g_hqn[4 * BATCH * DIM];         // qnorm'd gathered h (fp32)
__device__ float  g_hmean[1024];
__device__ float  g_hinvstd[1024];
__device__ float  g_hbias[4 * BATCH];             // per-(c,row) epilogue bias from shift
__device__ __half g_tA[4 * BATCH * DIM];          // fp16 A operand (t * scale)
__device__ __half g_EB[(size_t)4 * NPAD * DIM];   // fp16 B operand (qnorm'd E), padded

__device__ __forceinline__ uint32_t s2u(const void* p) {
    return (uint32_t)__cvta_generic_to_shared(p);
}

// --- 1: qnorm E -> fp16 table + partial stats; CTA b also handles h row b ---
__global__ void k_eqn(const float* __restrict__ E, const int* __restrict__ h_idx) {
    const int d = threadIdx.x;
    const int b = blockIdx.x;
    float s0 = 0.f, s1 = 0.f, s2 = 0.f, s3 = 0.f;
    float q0 = 0.f, q1 = 0.f, q2 = 0.f, q3 = 0.f;
    for (int n = b; n < NPAD; n += SCTAS) {
        const size_t o = (size_t)n * DIM + d;
        if (n < NENT) {
            float e0 = E[0 * (size_t)ECS + o];
            float e1 = E[1 * (size_t)ECS + o];
            float e2 = E[2 * (size_t)ECS + o];
            float e3 = E[3 * (size_t)ECS + o];
            float il = rsqrtf(e0 * e0 + e1 * e1 + e2 * e2 + e3 * e3);
            float c0 = e0 * il, c1 = e1 * il, c2 = e2 * il, c3 = e3 * il;
            g_EB[0 * (size_t)NPAD * DIM + o] = __float2half(c0);
            g_EB[1 * (size_t)NPAD * DIM + o] = __float2half(c1);
            g_EB[2 * (size_t)NPAD * DIM + o] = __float2half(c2);
            g_EB[3 * (size_t)NPAD * DIM + o] = __float2half(c3);
            s0 += c0; q0 += c0 * c0;
            s1 += c1; q1 += c1 * c1;
            s2 += c2; q2 += c2 * c2;
            s3 += c3; q3 += c3 * c3;
        } else {
            g_EB[0 * (size_t)NPAD * DIM + o] = __float2half(0.f);
            g_EB[1 * (size_t)NPAD * DIM + o] = __float2half(0.f);
            g_EB[2 * (size_t)NPAD * DIM + o] = __float2half(0.f);
            g_EB[3 * (size_t)NPAD * DIM + o] = __float2half(0.f);
        }
    }
    float* p = g_epart + b * 2048;
    p[0 * 512 + d * 2] = s0;  p[0 * 512 + d * 2 + 1] = q0;
    p[1 * 512 + d * 2] = s1;  p[1 * 512 + d * 2 + 1] = q1;
    p[2 * 512 + d * 2] = s2;  p[2 * 512 + d * 2 + 1] = q2;
    p[3 * 512 + d * 2] = s3;  p[3 * 512 + d * 2 + 1] = q3;

    // fused former k_hqn: gather + qnorm batch row b (SCTAS == BATCH)
    {
        const int n = h_idx[b];
        float e0 = E[0 * (size_t)ECS + (size_t)n * DIM + d];
        float e1 = E[1 * (size_t)ECS + (size_t)n * DIM + d];
        float e2 = E[2 * (size_t)ECS + (size_t)n * DIM + d];
        float e3 = E[3 * (size_t)ECS + (size_t)n * DIM + d];
        float il = rsqrtf(e0 * e0 + e1 * e1 + e2 * e2 + e3 * e3);
        g_hqn[0 * (BATCH * DIM) + b * DIM + d] = e0 * il;
        g_hqn[1 * (BATCH * DIM) + b * DIM + d] = e1 * il;
        g_hqn[2 * (BATCH * DIM) + b * DIM + d] = e2 * il;
        g_hqn[3 * (BATCH * DIM) + b * DIM + d] = e3 * il;
    }
}

// --- 2: merged stats finalize: blocks [0,1024) = E-stats fold; [1024,1056) = h BN ---
__global__ void k_stats(const float* __restrict__ gamma, const float* __restrict__ beta) {
    __shared__ float rs[256], rq[256];
    const int bx = blockIdx.x;
    const int i  = threadIdx.x;
    if (bx < 1024) {
        const int t = bx;
        float s = g_epart[i * 2048 + t * 2]     + g_epart[(i + 256) * 2048 + t * 2];
        float q = g_epart[i * 2048 + t * 2 + 1] + g_epart[(i + 256) * 2048 + t * 2 + 1];
        rs[i] = s; rq[i] = q;
        __syncthreads();
        for (int w = 128; w > 0; w >>= 1) {
            if (i < w) { rs[i] += rs[i + w]; rq[i] += rq[i + w]; }
            __syncthreads();
        }
        if (i == 0) {
            float mean = rs[0] * (1.f / NENT);
            float var  = rq[0] * (1.f / NENT) - mean * mean;
            float sc   = gamma[t] * rsqrtf(var + EPSF);
            g_escale[t] = sc;
            g_eshift[t] = beta[t] - mean * sc;
        }
    } else {
        const int blk = bx - 1024;
        const int c   = blk >> 3;
        const int d   = (blk & 7) * 32 + (i >> 3);
        const int j   = i & 7;
        float s = 0.f, q = 0.f;
        for (int b = j; b < BATCH; b += 8) {
            float v = g_hqn[c * (BATCH * DIM) + b * DIM + d];
            s += v; q += v * v;
        }
        rs[i] = s; rq[i] = q;
        __syncthreads();
        for (int w = 4; w > 0; w >>= 1) {
            if (j < w) { rs[i] += rs[i + w]; rq[i] += rq[i + w]; }
            __syncthreads();
        }
        if (j == 0) {
            float mean = rs[i] * (1.f / BATCH);
            float var  = rq[i] * (1.f / BATCH) - mean * mean;
            g_hmean[c * DIM + d]   = mean;
            g_hinvstd[c * DIM + d] = rsqrtf(var + EPSF);
        }
    }
}

// --- 3: BN(h), qnorm(r), quaternion mult -> fp16 A + hbias (shuffle reduce) ---
__global__ void k_t(const float* __restrict__ R, const float* __restrict__ psi,
                    const float* __restrict__ gamma, const float* __restrict__ beta,
                    const int* __restrict__ r_idx) {
    __shared__ float red[8][4];
    const int d = threadIdx.x;
    const int b = blockIdx.x;
    const int lid = d & 31, wrp = d >> 5;
    const int rid = r_idx[b];
    float h[4], r[4];
#pragma unroll
    for (int c = 0; c < 4; c++) {
        float v = g_hqn[c * (BATCH * DIM) + b * DIM + d];
        h[c] = (v - g_hmean[c * DIM + d]) * g_hinvstd[c * DIM + d] * gamma[c * DIM + d]
               + beta[c * DIM + d];
        r[c] = R[c * (size_t)RCS + (size_t)rid * DIM + d];
    }
    float il = rsqrtf(r[0] * r[0] + r[1] * r[1] + r[2] * r[2] + r[3] * r[3]);
    r[0] *= il; r[1] *= il; r[2] *= il; r[3] *= il;
    float p  = psi[(size_t)rid * DIM + d];
    float zc = cosf(p), zs = sinf(p);
    float m1r = h[0] * r[0] - h[1] * r[1];
    float m1i = h[0] * r[1] + h[1] * r[0];
    float Xr = h[2] * r[2] + h[3] * r[3];
    float Xi = h[3] * r[2] - h[2] * r[3];
    float m2r = zc * Xr - zs * Xi, m2i = zc * Xi + zs * Xr;
    float m3r = h[0] * r[2] - h[1] * r[3];
    float m3i = h[0] * r[3] + h[1] * r[2];
    float Yr = h[2] * r[0] + h[3] * r[1];
    float Yi = h[3] * r[0] - h[2] * r[1];
    float m4r = zc * Yr - zs * Yi, m4i = zc * Yi + zs * Yr;
    float t[4] = { m1r - m2r, m1i - m2i, m3r + m4r, m3i + m4i };

    float v[4];
#pragma unroll
    for (int c = 0; c < 4; c++) {
        float sc = g_escale[c * DIM + d], sh = g_eshift[c * DIM + d];
        g_tA[c * (BATCH * DIM) + b * DIM + d] = __float2half(t[c] * sc);
        v[c] = t[c] * sh;
#pragma unroll
        for (int o = 16; o > 0; o >>= 1)
            v[c] += __shfl_xor_sync(0xFFFFFFFFu, v[c], o);
    }
    if (lid == 0) {
        red[wrp][0] = v[0]; red[wrp][1] = v[1];
        red[wrp][2] = v[2]; red[wrp][3] = v[3];
    }
    __syncthreads();
    if (d < 4) {
        float s = 0.f;
#pragma unroll
        for (int w = 0; w < 8; w++) s += red[w][d];
        g_hbias[d * BATCH + b] = s;
    }
}

// --- 4: HMMA GEMM: 128x128 tile, 512 thr, 32x32 warp tile, 2 CTA/SM, 3-stage ---
#define KTILE 64
#define NTILE 128
#define STRIDE 72                         /* fp16 per smem row (64 + 8 pad)       */
#define AROWS 128
#define BROWS 128
#define AELEMS (AROWS * STRIDE)
#define STAGE_BYTES ((AROWS + BROWS) * STRIDE * 2)   /* 36864 */
#define NSTAGE 3
#define GEMM_SMEM (NSTAGE * STAGE_BYTES)             /* 110592; 2 CTAs = 221184  */
#define GTHREADS 512

__device__ __forceinline__ void ldmx4(uint32_t* r, uint32_t addr) {
    asm volatile(
        "ldmatrix.sync.aligned.m8n8.x4.shared.b16 {%0,%1,%2,%3}, [%4];"
        : "=r"(r[0]), "=r"(r[1]), "=r"(r[2]), "=r"(r[3]) : "r"(addr));
}

__device__ __forceinline__ void mma16816(float* c, const uint32_t* a,
                                         uint32_t b0, uint32_t b1) {
    asm volatile(
        "mma.sync.aligned.m16n8k16.row.col.f32.f16.f16.f32 "
        "{%0,%1,%2,%3}, {%4,%5,%6,%7}, {%8,%9}, {%0,%1,%2,%3};"
        : "+f"(c[0]), "+f"(c[1]), "+f"(c[2]), "+f"(c[3])
        : "r"(a[0]), "r"(a[1]), "r"(a[2]), "r"(a[3]), "r"(b0), "r"(b1));
}

// sigmoid(2*xh) = 0.5 + 0.5*tanh(xh): single MUFU.TANH.
__device__ __forceinline__ float fsig2(float xh) {
    float t;
    asm("tanh.approx.f32 %0, %1;" : "=f"(t) : "f"(xh));
    return fmaf(t, 0.5f, 0.5f);
}

__global__ void __launch_bounds__(GTHREADS, 2) k_gemm(const float* __restrict__ biases,
                                                      float* __restrict__ out) {
    extern __shared__ __align__(128) __half sh[];
    const int tid = threadIdx.x;
    const int lid = tid & 31, wid = tid >> 5;
    const int m0 = blockIdx.x * 128, n0 = blockIdx.y * NTILE, comp = blockIdx.z;
    const int wm = (wid & 3) * 32;      // 4 warps along m (32 rows each)
    const int wn = (wid >> 2) * 32;     // 4 warps along n (32 cols each)

    const __half* Ag = g_tA + ((size_t)comp * BATCH + m0) * DIM;
    const __half* Bg = g_EB + ((size_t)comp * NPAD + n0) * DIM;
    const uint32_t sbase = s2u(sh);

    // Stage fill: A 128 rows + B 128 rows, 8 x 16B chunks per row = 2048 chunks.
    auto load_stage = [&](int kc, int s) {
        const uint32_t sa = sbase + s * STAGE_BYTES;
        const uint32_t sb = sa + AELEMS * 2;
#pragma unroll
        for (int j = 0; j < 2; j++) {       // A: ids 0..1023
            int id = tid + j * GTHREADS;
            int row = id >> 3, c = id & 7;
            uint32_t da = sa + (row * STRIDE + c * 8) * 2;
            const __half* ga = Ag + row * DIM + kc * KTILE + c * 8;
            asm volatile("cp.async.cg.shared.global [%0], [%1], 16;"
                         :: "r"(da), "l"(ga));
        }
#pragma unroll
        for (int j = 0; j < 2; j++) {       // B: ids 0..1023
            int id = tid + j * GTHREADS;
            int row = id >> 3, c = id & 7;
            uint32_t db = sb + (row * STRIDE + c * 8) * 2;
            const __half* gb = Bg + row * DIM + kc * KTILE + c * 8;
            asm volatile("cp.async.cg.shared.global [%0], [%1], 16;"
                         :: "r"(db), "l"(gb));
        }
        asm volatile("cp.async.commit_group;" ::: "memory");
    };

    float acc[2][4][4];
#pragma unroll
    for (int mi = 0; mi < 2; mi++)
#pragma unroll
        for (int ni = 0; ni < 4; ni++)
#pragma unroll
            for (int f = 0; f < 4; f++) acc[mi][ni][f] = 0.f;

    load_stage(0, 0);
    load_stage(1, 1);

    const int lrow = lid & 15;
    const int lk   = (lid >> 4) * 8;

    // Per-warp smem base addresses (stage 0).
    const uint32_t aw = sbase + ((wm + lrow) * STRIDE + lk) * 2;
    const uint32_t bw = sbase + AELEMS * 2 + ((wn + lrow) * STRIDE + lk) * 2;

    // 3-stage ledger (R8-R11 proven): entering kc, committed {0..min(kc+1,3)}.
    // wait1 (kc<3) -> group kc done; prefetch kc+2 into stage (kc+2)%3 BEFORE
    // compute (that stage was consumed by chunk kc-1, finished pre-sync).
#pragma unroll 1
    for (int kc = 0; kc < 4; kc++) {
        if (kc < 3) {
            asm volatile("cp.async.wait_group 1;" ::: "memory");
        } else {
            asm volatile("cp.async.wait_group 0;" ::: "memory");
        }
        __syncthreads();
        if (kc < 2) load_stage(kc + 2, (kc + 2) % NSTAGE);

        const uint32_t soff = (uint32_t)(kc % NSTAGE) * STAGE_BYTES;
        const uint32_t sa = aw + soff;
        const uint32_t sb = bw + soff;
#pragma unroll
        for (int ks = 0; ks < 4; ks++) {
            uint32_t a[2][4], bf[2][4];
            ldmx4(a[0],  sa + ks * 32);
            ldmx4(a[1],  sa + 16 * STRIDE * 2 + ks * 32);
            ldmx4(bf[0], sb + ks * 32);
            ldmx4(bf[1], sb + 16 * STRIDE * 2 + ks * 32);
#pragma unroll
            for (int mi = 0; mi < 2; mi++)
#pragma unroll
                for (int ni = 0; ni < 4; ni++)
                    mma16816(acc[mi][ni], a[mi],
                             bf[ni >> 1][ni & 1], bf[ni >> 1][(ni & 1) + 2]);
        }
    }

    // ---- epilogue (mi-outer form): tanh sigmoid, float2 stores ----
    const float* bi = biases + (size_t)comp * NENT;
    float* op = out + (size_t)comp * BATCH * NENT;
#pragma unroll
    for (int mi = 0; mi < 2; mi++) {
        const int r0 = m0 + wm + mi * 16 + (lid >> 2);
        const float hb0 = 0.5f * g_hbias[comp * BATCH + r0];
        const float hb1 = 0.5f * g_hbias[comp * BATCH + r0 + 8];
#pragma unroll
        for (int ni = 0; ni < 4; ni++) {
            const int n = n0 + wn + ni * 8 + (lid & 3) * 2;
            if (n < NENT) {   // NENT even -> pair-level mask exact
                const float b0v = 0.5f * bi[n], b1v = 0.5f * bi[n + 1];
                float2 v0, v1;
                v0.x = fsig2(fmaf(acc[mi][ni][0], 0.5f, hb0 + b0v));
                v0.y = fsig2(fmaf(acc[mi][ni][1], 0.5f, hb0 + b1v));
                v1.x = fsig2(fmaf(acc[mi][ni][2], 0.5f, hb1 + b0v));
                v1.y = fsig2(fmaf(acc[mi][ni][3], 0.5f, hb1 + b1v));
                *reinterpret_cast<float2*>(op + (size_t)r0 * NENT + n) = v0;
                *reinterpret_cast<float2*>(op + (size_t)(r0 + 8) * NENT + n) = v1;
            }
        }
    }
}

// ---------------- launch ----------------
extern "C" void kernel_launch(void* const* d_in, const int* in_sizes, int n_in,
                              void* d_out, int out_size) {
    (void)in_sizes; (void)n_in; (void)out_size;
    const float* E      = (const float*)d_in[0];
    const float* R      = (const float*)d_in[1];
    const float* psi    = (const float*)d_in[2];
    const float* gamma  = (const float*)d_in[3];
    const float* beta   = (const float*)d_in[4];
    const float* biases = (const float*)d_in[5];
    const int*   h_idx  = (const int*)d_in[6];
    const int*   r_idx  = (const int*)d_in[7];
    float* out = (float*)d_out;

    cudaFuncSetAttribute(k_gemm, cudaFuncAttributeMaxDynamicSharedMemorySize,
                         GEMM_SMEM);

    k_eqn<<<SCTAS, DIM>>>(E, h_idx);
    k_stats<<<1056, 256>>>(gamma, beta);
    k_t<<<BATCH, DIM>>>(R, psi, gamma, beta, r_idx);
    k_gemm<<<dim3(4, NPAD / NTILE, 4), GTHREADS, GEMM_SMEM>>>(biases, out);
}